// round 1
// baseline (speedup 1.0000x reference)
#include <cuda_runtime.h>
#include <stdint.h>

// Problem constants (from reference): D=64, DC=64, OUT=64, GROUPS=4 -> CIN=192, GIN=48, GOUT=16
#define EDGE_BLOCKS 1184   // 148 SMs * 8
#define BN_EPS 1e-5f
#define MAX_CENTERS 4096

// Scratch (no allocations allowed)
__device__ float g_xc[MAX_CENTERS * 64];          // relu(grouped_linear(x_center))
__device__ float g_part[EDGE_BLOCKS * 128];       // per-block [sum(64) | sumsq(64)]
__device__ float g_bn[128];                       // [ |scale|(64) | shift(64) ]

// Order-preserving float<->uint encoding (unsigned compare == float compare).
// enc(x) >= 1 for all finite floats; 0 is a safe "empty" sentinel.
__device__ __forceinline__ unsigned enc_f(float x) {
    unsigned b = __float_as_uint(x);
    return (b & 0x80000000u) ? ~b : (b | 0x80000000u);
}
__device__ __forceinline__ float dec_f(unsigned u) {
    unsigned b = (u & 0x80000000u) ? (u ^ 0x80000000u) : ~u;
    return __uint_as_float(b);
}

__global__ void k_init(unsigned* __restrict__ o, int n) {
    int i = blockIdx.x * blockDim.x + threadIdx.x;
    if (i < n) o[i] = 0u;
}

// xc = relu(grouped_linear(x_center, W_c, b_c)); W_c: [4,16,16]
__global__ void k_centroid(const float* __restrict__ xcen, const float* __restrict__ Wc,
                           const float* __restrict__ bc, int C) {
    int tid = blockIdx.x * blockDim.x + threadIdx.x;
    if (tid >= C * 64) return;
    int c = tid & 63, ctr = tid >> 6;
    int g = c >> 4, o = c & 15;
    float h = bc[c];
    const float* xr = xcen + (size_t)ctr * 64 + g * 16;
    const float* wr = Wc + g * 256 + o;         // W_c[g][i][o], stride 16 over i
    #pragma unroll
    for (int i = 0; i < 16; i++) h += xr[i] * wr[i * 16];
    g_xc[tid] = fmaxf(h, 0.f);
}

// Fused edge pass: gather -> grouped GEMM -> (sum,sumsq partials) + atomicMax(enc(sign(gamma)*h))
__global__ void __launch_bounds__(256) k_edge(
    const float* __restrict__ x, const int* __restrict__ batch,
    const int* __restrict__ src, const int* __restrict__ dst,
    const float* __restrict__ Wv, const float* __restrict__ bv,
    const float* __restrict__ gamma, unsigned* __restrict__ outmax, int E)
{
    __shared__ float sm[4][192];   // 4 edges' m-vectors; rows 768B -> float4 aligned
    __shared__ float red[256];

    int c = threadIdx.x & 63;      // output channel
    int j = threadIdx.x >> 6;      // edge slot within block (0..3)
    int g = c >> 4, o = c & 15;

    // Per-thread weight column W_v[g, :, o] (48 floats) lives in registers.
    float w[48];
    #pragma unroll
    for (int i = 0; i < 48; i++) w[i] = __ldg(Wv + (g * 48 + i) * 16 + o);
    float bvc = __ldg(bv + c);
    float sgn = (__ldg(gamma + c) >= 0.f) ? 1.f : -1.f;

    float s1 = 0.f, s2 = 0.f;

    for (int e0 = blockIdx.x * 4; e0 < E; e0 += gridDim.x * 4) {
        int e = e0 + j;
        int d = -1;
        if (e < E) {
            int s = __ldg(src + e);
            d = __ldg(dst + e);
            int b = __ldg(batch + s);
            float xi = __ldg(x + (size_t)d * 64 + c);
            float xj = __ldg(x + (size_t)s * 64 + c);
            float yc = g_xc[b * 64 + c];
            sm[j][c]       = xi;        // m[0:64]   = x_i
            sm[j][64 + c]  = xj - xi;   // m[64:128] = x_j - x_i
            sm[j][128 + c] = yc;        // m[128:192]= y_j
        }
        __syncthreads();
        if (d >= 0) {
            const float4* mp = reinterpret_cast<const float4*>(&sm[j][g * 48]);
            float h = bvc;
            #pragma unroll
            for (int i = 0; i < 12; i++) {
                float4 v = mp[i];
                h += v.x * w[4*i] + v.y * w[4*i+1] + v.z * w[4*i+2] + v.w * w[4*i+3];
            }
            s1 += h;
            s2 += h * h;
            atomicMax(outmax + (size_t)d * 64 + c, enc_f(sgn * h));
        }
        __syncthreads();
    }

    // Deterministic per-block partial reduction (sum, sumsq) over the 4 edge slots.
    red[threadIdx.x] = s1;
    __syncthreads();
    if (j == 0) g_part[blockIdx.x * 128 + c] = red[c] + red[64 + c] + red[128 + c] + red[192 + c];
    __syncthreads();
    red[threadIdx.x] = s2;
    __syncthreads();
    if (j == 0) g_part[blockIdx.x * 128 + 64 + c] = red[c] + red[64 + c] + red[128 + c] + red[192 + c];
}

// Reduce partials -> mu/var -> |scale|, shift
__global__ void k_stats(const float* __restrict__ gamma, const float* __restrict__ beta, int E) {
    __shared__ float sm[128];
    int t = threadIdx.x;  // 128 threads
    float acc = 0.f;
    for (int b = 0; b < EDGE_BLOCKS; b++) acc += g_part[b * 128 + t];
    sm[t] = acc;
    __syncthreads();
    if (t < 64) {
        float S = sm[t], SQ = sm[64 + t];
        float inv = 1.f / (float)E;
        float mu  = S * inv;
        float var = fmaxf(SQ * inv - mu * mu, 0.f);
        float scale = gamma[t] * rsqrtf(var + BN_EPS);
        g_bn[t]      = fabsf(scale);          // pairs with sign(gamma) folded into encoding
        g_bn[64 + t] = beta[t] - mu * scale;
    }
}

// Decode encoded max, apply BN + relu, handle empty segments (sentinel 0 -> 0.0)
__global__ void k_final(float* __restrict__ out, int n) {
    int i = blockIdx.x * blockDim.x + threadIdx.x;
    if (i >= n) return;
    unsigned u = reinterpret_cast<unsigned*>(out)[i];
    int c = i & 63;
    float r = 0.f;
    if (u != 0u) {
        float f = dec_f(u);                        // = max_e sign(gamma_c) * h_e
        r = fmaxf(g_bn[c] * f + g_bn[64 + c], 0.f);
    }
    out[i] = r;
}

extern "C" void kernel_launch(void* const* d_in, const int* in_sizes, int n_in,
                              void* d_out, int out_size) {
    const float* x     = (const float*)d_in[0];
    const int*   batch = (const int*)  d_in[1];
    const int*   ei    = (const int*)  d_in[2];
    const float* xcen  = (const float*)d_in[3];
    /* d_in[4] = batch_center: unused by reference */
    const float* Wc    = (const float*)d_in[5];
    const float* bc    = (const float*)d_in[6];
    const float* Wv    = (const float*)d_in[7];
    const float* bv    = (const float*)d_in[8];
    const float* gamma = (const float*)d_in[9];
    const float* beta  = (const float*)d_in[10];

    int E = in_sizes[2] / 2;
    int C = in_sizes[3] / 64;
    int nout = out_size;  // N * 64

    k_init<<<(nout + 255) / 256, 256>>>((unsigned*)d_out, nout);
    k_centroid<<<(C * 64 + 255) / 256, 256>>>(xcen, Wc, bc, C);
    k_edge<<<EDGE_BLOCKS, 256>>>(x, batch, ei, ei + E, Wv, bv, gamma, (unsigned*)d_out, E);
    k_stats<<<1, 128>>>(gamma, beta, E);
    k_final<<<(nout + 255) / 256, 256>>>((float*)d_out, nout);
}

// round 3
// speedup vs baseline: 3.0218x; 3.0218x over previous
#include <cuda_runtime.h>
#include <stdint.h>
#include <math_constants.h>

// D=64, DC=64, OUT=64, GROUPS=4 -> CIN=192 (48 per group, 16 outs per group)
#define BN_EPS 1e-5f
#define MAX_N 65536
#define MAX_E (1 << 21)
#define MAX_CENTERS 1024

// ---- scratch (static device arrays only; no allocations) ----
__device__ float g_xc[MAX_CENTERS * 64];   // relu(grouped_linear(x_center))
__device__ float g_zc[MAX_CENTERS * 64];   // C . xc  per center
__device__ float g_A[64 * 64];             // [in][out] coeffs of x_i  (W1 - W2)
__device__ float g_B[64 * 64];             // coeffs of x_j (W2)
__device__ float g_C[64 * 64];             // coeffs of y_j (W3)
__device__ float g_sgn[64];                // sign(gamma_c)
__device__ float g_Q[MAX_N * 64];          // A.x + b per node (dst role)
__device__ float g_P[MAX_N * 64];          // B.x + Z[batch] per node (src role)
__device__ int   g_cnt[MAX_N + 1];
__device__ int   g_start[MAX_N + 1];
__device__ int   g_pos[MAX_N + 1];
__device__ int   g_sorted[MAX_E];          // src ids grouped by dst
__device__ float g_sum[128];               // [0:64) sum(h), [64:128) sum(h^2)
__device__ float g_bn[128];                // [0:64) scale, [64:128) shift

__global__ void k_zero(int N) {
    int i = blockIdx.x * blockDim.x + threadIdx.x;
    if (i <= N) g_cnt[i] = 0;
    if (i < 128) g_sum[i] = 0.f;
}

// xc = relu(grouped_linear(x_center, W_c, b_c)); W_c: [4,16,16]
__global__ void k_centroid(const float* __restrict__ xcen, const float* __restrict__ Wc,
                           const float* __restrict__ bc, int C) {
    int tid = blockIdx.x * blockDim.x + threadIdx.x;
    if (tid >= C * 64) return;
    int c = tid & 63, ctr = tid >> 6;
    int g = c >> 4, o = c & 15;
    float h = bc[c];
    const float* xr = xcen + (size_t)ctr * 64 + g * 16;
    const float* wr = Wc + g * 256 + o;
    #pragma unroll
    for (int i = 0; i < 16; i++) h += xr[i] * wr[i * 16];
    g_xc[tid] = fmaxf(h, 0.f);
}

// Build dense 64x64 matrices A,B,C from grouped W_v [4][48][16], plus sign(gamma).
__device__ __forceinline__ float Wk(const float* Wv, int k, int o) {
    int g = k / 48;
    return ((o >> 4) == g) ? Wv[g * 768 + (k % 48) * 16 + (o & 15)] : 0.f;
}
__global__ void k_mat(const float* __restrict__ Wv, const float* __restrict__ gamma) {
    int idx = blockIdx.x * blockDim.x + threadIdx.x;
    if (idx < 64) g_sgn[idx] = (gamma[idx] >= 0.f) ? 1.f : -1.f;
    if (idx >= 3 * 4096) return;
    int m = idx >> 12, r = idx & 4095;
    int i = r >> 6, o = r & 63;
    float v;
    if (m == 0)      v = Wk(Wv, i, o) - Wk(Wv, 64 + i, o);
    else if (m == 1) v = Wk(Wv, 64 + i, o);
    else             v = Wk(Wv, 128 + i, o);
    (m == 0 ? g_A : m == 1 ? g_B : g_C)[r] = v;
}

// Z[center] = C . xc[center]   (one warp-slot per center-row, warp-broadcast smem)
__global__ void __launch_bounds__(256) k_zc(int C) {
    __shared__ float sm[4][64];
    int c = threadIdx.x & 63, j = threadIdx.x >> 6;
    float w[64];
    #pragma unroll
    for (int i = 0; i < 64; i++) w[i] = g_C[i * 64 + c];
    for (int base = blockIdx.x * 4; base < C; base += gridDim.x * 4) {
        int ctr = base + j;
        bool ok = ctr < C;
        if (ok) sm[j][c] = g_xc[ctr * 64 + c];
        __syncthreads();
        if (ok) {
            const float4* mp = reinterpret_cast<const float4*>(sm[j]);
            float acc = 0.f;
            #pragma unroll
            for (int i = 0; i < 16; i++) {
                float4 v = mp[i];
                acc += v.x * w[4*i] + v.y * w[4*i+1] + v.z * w[4*i+2] + v.w * w[4*i+3];
            }
            g_zc[ctr * 64 + c] = acc;
        }
        __syncthreads();
    }
}

__global__ void k_hist(const int* __restrict__ dst, int E) {
    int e = blockIdx.x * blockDim.x + threadIdx.x;
    if (e < E) atomicAdd(&g_cnt[dst[e]], 1);
}

// single-block exclusive scan of g_cnt[0..N) -> g_start, g_pos; g_start[N]=E
__global__ void k_scan(int N) {
    __shared__ int warp_sums[32];
    __shared__ int carry_s;
    int tid = threadIdx.x, lane = tid & 31, w = tid >> 5;
    int carry = 0;
    for (int tile = 0; tile < N; tile += 1024) {
        int i = tile + tid;
        int v = (i < N) ? g_cnt[i] : 0;
        int x = v;
        #pragma unroll
        for (int d = 1; d < 32; d <<= 1) {
            int y = __shfl_up_sync(0xffffffffu, x, d);
            if (lane >= d) x += y;
        }
        if (lane == 31) warp_sums[w] = x;
        __syncthreads();
        if (w == 0) {
            int s = warp_sums[lane];
            #pragma unroll
            for (int d = 1; d < 32; d <<= 1) {
                int y = __shfl_up_sync(0xffffffffu, s, d);
                if (lane >= d) s += y;
            }
            warp_sums[lane] = s;
        }
        __syncthreads();
        int incl = x + (w > 0 ? warp_sums[w - 1] : 0) + carry;
        int excl = incl - v;
        if (i < N) { g_start[i] = excl; g_pos[i] = excl; }
        if (tid == 1023) carry_s = incl;
        __syncthreads();
        carry = carry_s;
        __syncthreads();
    }
    if (tid == 0) g_start[N] = carry;
}

__global__ void k_scatter(const int* __restrict__ src, const int* __restrict__ dst, int E) {
    int e = blockIdx.x * blockDim.x + threadIdx.x;
    if (e < E) {
        int p = atomicAdd(&g_pos[dst[e]], 1);
        g_sorted[p] = src[e];
    }
}

// ---- per-node transforms: thread owns output channel c, weight column in regs ----
// MODE 0: Q = A.x + b_v          MODE 1: P = B.x + Z[batch]
template <int MODE>
__global__ void __launch_bounds__(256) k_node(const float* __restrict__ x,
                                              const int* __restrict__ batch,
                                              const float* __restrict__ bv, int N) {
    __shared__ float sm[4][64];
    int c = threadIdx.x & 63, j = threadIdx.x >> 6;
    const float* M = (MODE == 0) ? g_A : g_B;
    float w[64];
    #pragma unroll
    for (int i = 0; i < 64; i++) w[i] = M[i * 64 + c];
    float bias = (MODE == 0) ? __ldg(&bv[c]) : 0.f;

    for (int base = blockIdx.x * 4; base < N; base += gridDim.x * 4) {
        int node = base + j;
        bool ok = node < N;
        float extra = 0.f;
        if (ok) {
            sm[j][c] = __ldg(&x[(size_t)node * 64 + c]);
            if (MODE == 1) {
                int b = __ldg(&batch[node]);
                extra = g_zc[b * 64 + c];
            }
        }
        __syncthreads();
        if (ok) {
            const float4* mp = reinterpret_cast<const float4*>(sm[j]);
            float acc = bias + extra;
            #pragma unroll
            for (int i = 0; i < 16; i++) {
                float4 v = mp[i];   // warp-broadcast: all lanes same address
                acc += v.x * w[4*i] + v.y * w[4*i+1] + v.z * w[4*i+2] + v.w * w[4*i+3];
            }
            size_t oi = (size_t)node * 64 + c;
            if (MODE == 0) g_Q[oi] = acc;
            else           g_P[oi] = acc;
        }
        __syncthreads();
    }
}

// ---- segment max + BN statistics: one warp per dst node, no output atomics ----
__global__ void __launch_bounds__(256) k_segmax(float* __restrict__ out, int N) {
    int warp = (blockIdx.x * blockDim.x + threadIdx.x) >> 5;
    int lane = threadIdx.x & 31;
    float s1a = 0.f, s1b = 0.f, s2a = 0.f, s2b = 0.f;
    int d = warp;
    if (d < N) {
        int beg = g_start[d], end = g_start[d + 1];
        float q0 = g_Q[d * 64 + lane], q1 = g_Q[d * 64 + 32 + lane];
        float sg0 = g_sgn[lane], sg1 = g_sgn[32 + lane];
        float m0 = -CUDART_INF_F, m1 = -CUDART_INF_F;
        #pragma unroll 4
        for (int e = beg; e < end; e++) {
            int s = __ldg(&g_sorted[e]);
            float p0 = __ldg(&g_P[s * 64 + lane]);
            float p1 = __ldg(&g_P[s * 64 + 32 + lane]);
            float h0 = q0 + p0, h1 = q1 + p1;
            s1a += h0; s1b += h1;
            s2a = fmaf(h0, h0, s2a); s2b = fmaf(h1, h1, s2b);
            m0 = fmaxf(m0, sg0 * h0); m1 = fmaxf(m1, sg1 * h1);
        }
        out[d * 64 + lane] = m0;          // raw signed max (-inf if no edges)
        out[d * 64 + 32 + lane] = m1;
    }
    // block-level stats reduction -> 128 atomicAdds per block
    __shared__ float red[8][128];
    int w = threadIdx.x >> 5;
    red[w][lane] = s1a; red[w][32 + lane] = s1b;
    red[w][64 + lane] = s2a; red[w][96 + lane] = s2b;
    __syncthreads();
    if (threadIdx.x < 128) {
        float t = 0.f;
        #pragma unroll
        for (int i = 0; i < 8; i++) t += red[i][threadIdx.x];
        atomicAdd(&g_sum[threadIdx.x], t);
    }
}

__global__ void k_stats(const float* __restrict__ gamma, const float* __restrict__ beta, int E) {
    int c = threadIdx.x;   // 64 threads
    if (c >= 64) return;
    float S = g_sum[c], SQ = g_sum[64 + c];
    float inv = 1.f / (float)E;
    float mu = S * inv;
    float var = fmaxf(SQ * inv - mu * mu, 0.f);
    float scale = gamma[c] * rsqrtf(var + BN_EPS);
    g_bn[c] = fabsf(scale);              // pairs with sign(gamma) folded into max
    g_bn[64 + c] = beta[c] - mu * scale;
}

__global__ void k_final(float* __restrict__ out, int n) {
    int i = blockIdx.x * blockDim.x + threadIdx.x;
    if (i >= n) return;
    float v = out[i];
    int c = i & 63;
    out[i] = isinf(v) ? 0.f : fmaxf(g_bn[c] * v + g_bn[64 + c], 0.f);
}

extern "C" void kernel_launch(void* const* d_in, const int* in_sizes, int n_in,
                              void* d_out, int out_size) {
    const float* x     = (const float*)d_in[0];
    const int*   batch = (const int*)  d_in[1];
    const int*   ei    = (const int*)  d_in[2];
    const float* xcen  = (const float*)d_in[3];
    const float* Wc    = (const float*)d_in[5];
    const float* bc    = (const float*)d_in[6];
    const float* Wv    = (const float*)d_in[7];
    const float* bv    = (const float*)d_in[8];
    const float* gamma = (const float*)d_in[9];
    const float* beta  = (const float*)d_in[10];

    int E = in_sizes[2] / 2;
    int C = in_sizes[3] / 64;
    int nout = out_size;          // N * 64
    int N = nout / 64;
    const int* src = ei;
    const int* dst = ei + E;

    k_zero<<<(N + 256) / 256, 256>>>(N);
    k_centroid<<<(C * 64 + 255) / 256, 256>>>(xcen, Wc, bc, C);
    k_mat<<<(3 * 4096 + 255) / 256, 256>>>(Wv, gamma);
    k_zc<<<256, 256>>>(C);
    k_hist<<<(E + 255) / 256, 256>>>(dst, E);
    k_scan<<<1, 1024>>>(N);
    k_scatter<<<(E + 255) / 256, 256>>>(src, dst, E);
    k_node<0><<<1184, 256>>>(x, batch, bv, N);
    k_node<1><<<1184, 256>>>(x, batch, bv, N);
    k_segmax<<<(N + 7) / 8, 256>>>((float*)d_out, N);
    k_stats<<<1, 64>>>(gamma, beta, E);
    k_final<<<(nout + 255) / 256, 256>>>((float*)d_out, nout);
}

// round 10
// speedup vs baseline: 3.6570x; 1.2102x over previous
#include <cuda_runtime.h>
#include <stdint.h>
#include <math_constants.h>

// D=64, DC=64, OUT=64, GROUPS=4 -> CIN=192 (48 per group, 16 outs per group)
#define BN_EPS 1e-5f
#define MAX_N 65536
#define MAX_E (1 << 21)
#define MAX_CENTERS 1024

// ---- scratch (static device arrays only; no allocations) ----
__device__ float g_xc[MAX_CENTERS * 64];   // relu(grouped_linear(x_center))
__device__ float g_zc[MAX_CENTERS * 64];   // C . xc  per center
__device__ float g_A[64 * 64];             // [in][out] coeffs of x_i  (W1 - W2)
__device__ float g_B[64 * 64];             // coeffs of x_j (W2)
__device__ float g_C[64 * 64];             // coeffs of y_j (W3)
__device__ float g_sgn[64];                // sign(gamma_c)
__device__ float g_Q[MAX_N * 64];          // A.x + b per node (dst role)
__device__ float g_P[MAX_N * 64];          // B.x + Z[batch] per node (src role)
__device__ int   g_cnt[MAX_N + 1];
__device__ int   g_start[MAX_N + 1];
__device__ int   g_pos[MAX_N + 1];
__device__ int   g_bsum[1024];             // per-1024-tile totals (<=64 used)
__device__ int   g_boff[1024];             // exclusive offsets of tiles
__device__ int   g_sorted[MAX_E];          // src ids grouped by dst
__device__ float g_sum[128];               // [0:64) sum(h), [64:128) sum(h^2)
__device__ float g_bn[128];                // [0:64) |scale|, [64:128) shift

__global__ void k_zero(int N) {
    int i = blockIdx.x * blockDim.x + threadIdx.x;
    if (i <= N) g_cnt[i] = 0;
    if (i < 128) g_sum[i] = 0.f;
}

// xc = relu(grouped_linear(x_center, W_c, b_c)); W_c: [4,16,16]
__global__ void k_centroid(const float* __restrict__ xcen, const float* __restrict__ Wc,
                           const float* __restrict__ bc, int C) {
    int tid = blockIdx.x * blockDim.x + threadIdx.x;
    if (tid >= C * 64) return;
    int c = tid & 63, ctr = tid >> 6;
    int g = c >> 4, o = c & 15;
    float h = bc[c];
    const float* xr = xcen + (size_t)ctr * 64 + g * 16;
    const float* wr = Wc + g * 256 + o;
    #pragma unroll
    for (int i = 0; i < 16; i++) h += xr[i] * wr[i * 16];
    g_xc[tid] = fmaxf(h, 0.f);
}

// Build dense 64x64 matrices A,B,C from grouped W_v [4][48][16], plus sign(gamma).
__device__ __forceinline__ float Wk(const float* Wv, int k, int o) {
    int g = k / 48;
    return ((o >> 4) == g) ? Wv[g * 768 + (k % 48) * 16 + (o & 15)] : 0.f;
}
__global__ void k_mat(const float* __restrict__ Wv, const float* __restrict__ gamma) {
    int idx = blockIdx.x * blockDim.x + threadIdx.x;
    if (idx < 64) g_sgn[idx] = (gamma[idx] >= 0.f) ? 1.f : -1.f;
    if (idx >= 3 * 4096) return;
    int m = idx >> 12, r = idx & 4095;
    int i = r >> 6, o = r & 63;
    float v;
    if (m == 0)      v = Wk(Wv, i, o) - Wk(Wv, 64 + i, o);
    else if (m == 1) v = Wk(Wv, 64 + i, o);
    else             v = Wk(Wv, 128 + i, o);
    (m == 0 ? g_A : m == 1 ? g_B : g_C)[r] = v;
}

// Z[center] = C . xc[center]
__global__ void __launch_bounds__(256) k_zc(int C) {
    __shared__ float sm[4][64];
    int c = threadIdx.x & 63, j = threadIdx.x >> 6;
    float w[64];
    #pragma unroll
    for (int i = 0; i < 64; i++) w[i] = g_C[i * 64 + c];
    for (int base = blockIdx.x * 4; base < C; base += gridDim.x * 4) {
        int ctr = base + j;
        bool ok = ctr < C;
        if (ok) sm[j][c] = g_xc[ctr * 64 + c];
        __syncthreads();
        if (ok) {
            const float4* mp = reinterpret_cast<const float4*>(sm[j]);
            float acc = 0.f;
            #pragma unroll
            for (int i = 0; i < 16; i++) {
                float4 v = mp[i];
                acc += v.x * w[4*i] + v.y * w[4*i+1] + v.z * w[4*i+2] + v.w * w[4*i+3];
            }
            g_zc[ctr * 64 + c] = acc;
        }
        __syncthreads();
    }
}

__global__ void k_hist(const int* __restrict__ dst, int E) {
    int e = blockIdx.x * blockDim.x + threadIdx.x;
    if (e < E) atomicAdd(&g_cnt[dst[e]], 1);
}

// ---- hierarchical scan: tile sums -> tiny scan -> tile rescan ----
__global__ void k_bsum(int N) {
    __shared__ int wred[32];
    int i = blockIdx.x * 1024 + threadIdx.x;
    int v = (i < N) ? g_cnt[i] : 0;
    #pragma unroll
    for (int d = 16; d > 0; d >>= 1) v += __shfl_down_sync(0xffffffffu, v, d);
    int lane = threadIdx.x & 31, w = threadIdx.x >> 5;
    if (lane == 0) wred[w] = v;
    __syncthreads();
    if (w == 0) {
        int s = wred[lane];
        #pragma unroll
        for (int d = 16; d > 0; d >>= 1) s += __shfl_down_sync(0xffffffffu, s, d);
        if (lane == 0) g_bsum[blockIdx.x] = s;
    }
}

__global__ void k_scanb(int NB) {
    // single block, 1024 threads; NB <= 64
    __shared__ int ws[32];
    int tid = threadIdx.x, lane = tid & 31, w = tid >> 5;
    int v = (tid < NB) ? g_bsum[tid] : 0;
    int x = v;
    #pragma unroll
    for (int d = 1; d < 32; d <<= 1) {
        int y = __shfl_up_sync(0xffffffffu, x, d);
        if (lane >= d) x += y;
    }
    if (lane == 31) ws[w] = x;
    __syncthreads();
    if (w == 0) {
        int s = ws[lane];
        #pragma unroll
        for (int d = 1; d < 32; d <<= 1) {
            int y = __shfl_up_sync(0xffffffffu, s, d);
            if (lane >= d) s += y;
        }
        ws[lane] = s;
    }
    __syncthreads();
    if (tid < NB) g_boff[tid] = x - v + (w > 0 ? ws[w - 1] : 0);
}

__global__ void k_scanfin(int N, int E) {
    __shared__ int ws[32];
    int tid = threadIdx.x, lane = tid & 31, w = tid >> 5;
    int i = blockIdx.x * 1024 + tid;
    int v = (i < N) ? g_cnt[i] : 0;
    int x = v;
    #pragma unroll
    for (int d = 1; d < 32; d <<= 1) {
        int y = __shfl_up_sync(0xffffffffu, x, d);
        if (lane >= d) x += y;
    }
    if (lane == 31) ws[w] = x;
    __syncthreads();
    if (w == 0) {
        int s = ws[lane];
        #pragma unroll
        for (int d = 1; d < 32; d <<= 1) {
            int y = __shfl_up_sync(0xffffffffu, s, d);
            if (lane >= d) s += y;
        }
        ws[lane] = s;
    }
    __syncthreads();
    if (i < N) {
        int excl = x - v + (w > 0 ? ws[w - 1] : 0) + g_boff[blockIdx.x];
        g_start[i] = excl;
        g_pos[i] = excl;
    }
    if (blockIdx.x == 0 && tid == 0) g_start[N] = E;
}

__global__ void k_scatter(const int* __restrict__ src, const int* __restrict__ dst, int E) {
    int e = blockIdx.x * blockDim.x + threadIdx.x;
    if (e < E) {
        int p = atomicAdd(&g_pos[dst[e]], 1);
        g_sorted[p] = src[e];
    }
}

// ---- fused per-node transform: Q = A.x + b_v  and  P = B.x + Z[batch] ----
__global__ void __launch_bounds__(256) k_node(const float* __restrict__ x,
                                              const int* __restrict__ batch,
                                              const float* __restrict__ bv, int N) {
    __shared__ float sm[4][64];
    int c = threadIdx.x & 63, j = threadIdx.x >> 6;
    float wa[64], wb[64];
    #pragma unroll
    for (int i = 0; i < 64; i++) { wa[i] = g_A[i * 64 + c]; wb[i] = g_B[i * 64 + c]; }
    float bias = __ldg(&bv[c]);

    for (int base = blockIdx.x * 4; base < N; base += gridDim.x * 4) {
        int node = base + j;
        bool ok = node < N;
        float extra = 0.f;
        if (ok) {
            sm[j][c] = __ldg(&x[(size_t)node * 64 + c]);
            int b = __ldg(&batch[node]);
            extra = g_zc[b * 64 + c];
        }
        __syncthreads();
        if (ok) {
            const float4* mp = reinterpret_cast<const float4*>(sm[j]);
            float a0 = bias, a1 = extra;
            #pragma unroll
            for (int i = 0; i < 16; i++) {
                float4 v = mp[i];   // warp-broadcast
                a0 += v.x * wa[4*i] + v.y * wa[4*i+1] + v.z * wa[4*i+2] + v.w * wa[4*i+3];
                a1 += v.x * wb[4*i] + v.y * wb[4*i+1] + v.z * wb[4*i+2] + v.w * wb[4*i+3];
            }
            size_t oi = (size_t)node * 64 + c;
            g_Q[oi] = a0;
            g_P[oi] = a1;
        }
        __syncthreads();
    }
}

// ---- segment max + BN statistics: one warp per dst node, no output atomics ----
__global__ void __launch_bounds__(256) k_segmax(float* __restrict__ out, int N) {
    int warp = (blockIdx.x * blockDim.x + threadIdx.x) >> 5;
    int lane = threadIdx.x & 31;
    float s1a = 0.f, s1b = 0.f, s2a = 0.f, s2b = 0.f;
    int d = warp;
    if (d < N) {
        int beg = g_start[d], end = g_start[d + 1];
        float q0 = g_Q[d * 64 + lane], q1 = g_Q[d * 64 + 32 + lane];
        float sg0 = g_sgn[lane], sg1 = g_sgn[32 + lane];
        float m0 = -CUDART_INF_F, m1 = -CUDART_INF_F;
        #pragma unroll 4
        for (int e = beg; e < end; e++) {
            int s = __ldg(&g_sorted[e]);
            float p0 = __ldg(&g_P[s * 64 + lane]);
            float p1 = __ldg(&g_P[s * 64 + 32 + lane]);
            float h0 = q0 + p0, h1 = q1 + p1;
            s1a += h0; s1b += h1;
            s2a = fmaf(h0, h0, s2a); s2b = fmaf(h1, h1, s2b);
            m0 = fmaxf(m0, sg0 * h0); m1 = fmaxf(m1, sg1 * h1);
        }
        out[d * 64 + lane] = m0;          // raw signed max (-inf if no edges)
        out[d * 64 + 32 + lane] = m1;
    }
    __shared__ float red[8][128];
    int w = threadIdx.x >> 5;
    red[w][lane] = s1a; red[w][32 + lane] = s1b;
    red[w][64 + lane] = s2a; red[w][96 + lane] = s2b;
    __syncthreads();
    if (threadIdx.x < 128) {
        float t = 0.f;
        #pragma unroll
        for (int i = 0; i < 8; i++) t += red[i][threadIdx.x];
        atomicAdd(&g_sum[threadIdx.x], t);
    }
}

__global__ void k_stats(const float* __restrict__ gamma, const float* __restrict__ beta, int E) {
    int c = threadIdx.x;   // 64 threads
    if (c >= 64) return;
    float S = g_sum[c], SQ = g_sum[64 + c];
    float inv = 1.f / (float)E;
    float mu = S * inv;
    float var = fmaxf(SQ * inv - mu * mu, 0.f);
    float scale = gamma[c] * rsqrtf(var + BN_EPS);
    g_bn[c] = fabsf(scale);              // pairs with sign(gamma) folded into max
    g_bn[64 + c] = beta[c] - mu * scale;
}

__global__ void k_final(float* __restrict__ out, int n) {
    int i = blockIdx.x * blockDim.x + threadIdx.x;
    if (i >= n) return;
    float v = out[i];
    int c = i & 63;
    out[i] = isinf(v) ? 0.f : fmaxf(g_bn[c] * v + g_bn[64 + c], 0.f);
}

extern "C" void kernel_launch(void* const* d_in, const int* in_sizes, int n_in,
                              void* d_out, int out_size) {
    const float* x     = (const float*)d_in[0];
    const int*   batch = (const int*)  d_in[1];
    const int*   ei    = (const int*)  d_in[2];
    const float* xcen  = (const float*)d_in[3];
    const float* Wc    = (const float*)d_in[5];
    const float* bc    = (const float*)d_in[6];
    const float* Wv    = (const float*)d_in[7];
    const float* bv    = (const float*)d_in[8];
    const float* gamma = (const float*)d_in[9];
    const float* beta  = (const float*)d_in[10];

    int E = in_sizes[2] / 2;
    int C = in_sizes[3] / 64;
    int nout = out_size;          // N * 64
    int N = nout / 64;
    int NB = (N + 1023) / 1024;
    const int* src = ei;
    const int* dst = ei + E;

    k_zero<<<(N + 256) / 256, 256>>>(N);
    k_centroid<<<(C * 64 + 255) / 256, 256>>>(xcen, Wc, bc, C);
    k_mat<<<(3 * 4096 + 255) / 256, 256>>>(Wv, gamma);
    k_zc<<<256, 256>>>(C);
    k_hist<<<(E + 255) / 256, 256>>>(dst, E);
    k_bsum<<<NB, 1024>>>(N);
    k_scanb<<<1, 1024>>>(NB);
    k_scanfin<<<NB, 1024>>>(N, E);
    k_scatter<<<(E + 255) / 256, 256>>>(src, dst, E);
    k_node<<<1184, 256>>>(x, batch, bv, N);
    k_segmax<<<(N + 7) / 8, 256>>>((float*)d_out, N);
    k_stats<<<1, 64>>>(gamma, beta, E);
    k_final<<<(nout + 255) / 256, 256>>>((float*)d_out, nout);
}